// round 13
// baseline (speedup 1.0000x reference)
#include <cuda_runtime.h>
#include <cuda_fp16.h>
#include <cstdint>

// ---------------- problem constants ----------------
#define BB    8
#define CINC  128
#define COUT  128
#define HH    64
#define WW    64
#define HW    4096
#define KK    9
#define NPHASE 9       // K = 1152 = 9 phases of 128 (phase == tap)
#define NPIX  64       // pixels per CTA (1 output row)
#define KPADH 136      // padded row length in halves (272B rows -> LDSM/STS conflict-free)
#define NSTAGE 3       // pipeline depth

// ---------------- dynamic smem layout (bytes) ----------------
#define OFF_IDX  0                         // ushort4[9*64] = 4608
#define OFF_WGT  4608                      // uint4[9*64]   = 9216 -> 13824
#define VTILE_BYTES (NPIX * KPADH * 2)     // 17408
#define OFF_V0   13824
#define SMEM_TOTAL (OFF_V0 + NSTAGE * VTILE_BYTES)  // 66048

// weights pre-permuted into m16n8k16 fp16 A-fragment order
__device__ uint4 g_wfh[72 * 8 * 32];
// NHWC-tiled x in fp16: g_xh[b][cinhalf(2)][yx][cin64]  (8 MB)
__device__ __half g_xh[BB * 2 * HW * 64];

__device__ __forceinline__ void mma_f16(float* d, const uint4 a, uint32_t b0, uint32_t b1) {
    asm volatile(
        "mma.sync.aligned.m16n8k16.row.col.f32.f16.f16.f32 "
        "{%0,%1,%2,%3}, {%4,%5,%6,%7}, {%8,%9}, {%0,%1,%2,%3};"
        : "+f"(d[0]), "+f"(d[1]), "+f"(d[2]), "+f"(d[3])
        : "r"(a.x), "r"(a.y), "r"(a.z), "r"(a.w), "r"(b0), "r"(b1));
}

__device__ __forceinline__ uint32_t smem_u32(const void* p) {
    uint32_t a;
    asm("{ .reg .u64 t; cvta.to.shared.u64 t, %1; cvt.u32.u64 %0, t; }" : "=r"(a) : "l"(p));
    return a;
}

#define BAR_SYNC(id)   asm volatile("bar.sync %0, 256;"   :: "r"(id) : "memory")
#define BAR_ARRIVE(id) asm volatile("bar.arrive %0, 256;" :: "r"(id) : "memory")
#define MEMBAR_CTA()   asm volatile("membar.cta;" ::: "memory")

// ---------------- merged prep: x transpose (blocks 0..2047) + weight permute (2048..2119) ----
__global__ void prep_all_kernel(const float* __restrict__ x,
                                const float* __restrict__ weight) {
    __shared__ float ts[32][65];
    const int bid = blockIdx.x;
    const int tid = threadIdx.x;

    if (bid < 2048) {
        // x transpose: NCHW f32 -> [b][cinhalf][yx][cin64] fp16
        const int yxt = bid & 63;
        const int blk = (bid >> 6) & 3;
        const int b   = bid >> 8;
        const int yx0 = yxt * 64;

        const int yxl = tid & 63, cl = tid >> 6;
        const float* src = x + (((size_t)(b * CINC + blk * 32)) << 12) + yx0 + yxl;
        #pragma unroll
        for (int i = 0; i < 8; i++) {
            const int c = cl + i * 4;
            ts[c][yxl] = src[(size_t)c << 12];
        }
        __syncthreads();

        __half* dst = g_xh + ((((size_t)(b * 2 + (blk >> 1)) << 12) + yx0) << 6)
                    + ((blk & 1) << 5);
        const int c2 = tid & 31, yq = tid >> 5;
        #pragma unroll
        for (int i = 0; i < 8; i++) {
            const int yx = yq + i * 8;
            dst[(size_t)yx * 64 + c2] = __float2half(ts[c2][yx]);
        }
    } else {
        // weight prep: fp16 round + A-fragment permutation
        const int t = (bid - 2048) * 256 + tid;
        const int lane = t & 31;
        const int mb   = (t >> 5) & 7;
        const int ks   = (t >> 8) & 1;
        const int c    = t >> 9;
        const int grp = lane >> 2, t4 = lane & 3;
        const int tap = c >> 2;
        const int cb  = ((c & 3) << 5) + ks * 16;
        const int kA  = cb + t4 * 2;
        const int kB  = kA + 8;
        const int co0 = mb * 16 + grp;
        const int co1 = co0 + 8;
        #define WF(co, cin) __float2half_rn(weight[((co) * CINC + (cin)) * KK + tap])
        __half2 a0 = __halves2half2(WF(co0, kA), WF(co0, kA + 1));
        __half2 a1 = __halves2half2(WF(co1, kA), WF(co1, kA + 1));
        __half2 a2 = __halves2half2(WF(co0, kB), WF(co0, kB + 1));
        __half2 a3 = __halves2half2(WF(co1, kB), WF(co1, kB + 1));
        #undef WF
        uint4 u;
        u.x = *(uint32_t*)&a0; u.y = *(uint32_t*)&a1;
        u.z = *(uint32_t*)&a2; u.w = *(uint32_t*)&a3;
        g_wfh[t] = u;
    }
}

// ---------------- main kernel: 256 threads; warps 0-3 mma, warps 4-7 gather ----------------
__global__ __launch_bounds__(256, 2)
void deform_conv_mma_kernel(const float* __restrict__ offs,
                            const float* __restrict__ bias,
                            float* __restrict__ out)
{
    extern __shared__ char smem[];
    ushort4* sIdx = (ushort4*)(smem + OFF_IDX);
    uint4*   sWgt = (uint4*)(smem + OFF_WGT);
    const uint32_t sb = smem_u32(smem);

    const int tid  = threadIdx.x;
    const int wid  = tid >> 5;
    const int lane = tid & 31;

    const int b  = blockIdx.x >> 6;       // 64 CTAs per image (1 row each)
    const int ho = blockIdx.x & 63;       // output row

    // ---- 1. sampling tables: 9 taps x 64 pix (all 256 threads) ----
    for (int e = tid; e < KK * NPIX; e += 256) {
        const int t  = e >> 6;
        const int wo = e & 63;
        const int kh = t / 3;
        const int kw = t - kh * 3;
        const float* ob = offs + (((size_t)b * (2 * KK) + 2 * t) * HH + ho) * WW + wo;
        const float dy = ob[0];
        const float dx = ob[HW];
        const float py = (float)(ho - 1 + kh) + dy;
        const float px = (float)(wo - 1 + kw) + dx;
        const float y0f = floorf(py), x0f = floorf(px);
        const float ly = py - y0f, lx = px - x0f;
        const int y0 = (int)y0f, x0 = (int)x0f;
        const float wy0 = (y0 >= 0     && y0 < HH)     ? (1.0f - ly) : 0.0f;
        const float wy1 = (y0 + 1 >= 0 && y0 + 1 < HH) ? ly          : 0.0f;
        const float wx0 = (x0 >= 0     && x0 < WW)     ? (1.0f - lx) : 0.0f;
        const float wx1 = (x0 + 1 >= 0 && x0 + 1 < WW) ? lx          : 0.0f;
        const int cy0 = min(max(y0, 0), HH - 1), cy1 = min(max(y0 + 1, 0), HH - 1);
        const int cx0 = min(max(x0, 0), WW - 1), cx1 = min(max(x0 + 1, 0), WW - 1);
        sIdx[e] = make_ushort4((unsigned short)(cy0 * WW + cx0),
                               (unsigned short)(cy0 * WW + cx1),
                               (unsigned short)(cy1 * WW + cx0),
                               (unsigned short)(cy1 * WW + cx1));
        const __half2 h0 = __float2half2_rn(wy0 * wx0);
        const __half2 h1 = __float2half2_rn(wy0 * wx1);
        const __half2 h2 = __float2half2_rn(wy1 * wx0);
        const __half2 h3 = __float2half2_rn(wy1 * wx1);
        uint4 wq;
        wq.x = *(const uint32_t*)&h0; wq.y = *(const uint32_t*)&h1;
        wq.z = *(const uint32_t*)&h2; wq.w = *(const uint32_t*)&h3;
        sWgt[e] = wq;
    }
    __syncthreads();

    if (wid >= 4) {
        // ================= PRODUCER: warps 4-7 (128 threads) =================
        const int ptid  = tid & 127;
        const int pixg  = ptid >> 3;          // pixel group 0..15
        const int lane8 = ptid & 7;           // cin octet within 64

        for (int c = 0; c < NPHASE; c++) {
            const int s = c % NSTAGE;
            if (c >= NSTAGE) BAR_SYNC(4 + s);   // wait consumers done with buffer s

            char* vb = smem + OFF_V0 + s * VTILE_BYTES;
            #pragma unroll
            for (int pass = 0; pass < 4; pass++) {
                const int pix = pass * 16 + pixg;
                const int e   = c * 64 + pix;
                const ushort4 q = sIdx[e];
                const uint4   wq = sWgt[e];
                const __half2 w0 = *(const __half2*)&wq.x;
                const __half2 w1 = *(const __half2*)&wq.y;
                const __half2 w2 = *(const __half2*)&wq.z;
                const __half2 w3 = *(const __half2*)&wq.w;
                #pragma unroll
                for (int half64 = 0; half64 < 2; half64++) {
                    const __half* pl = g_xh + ((size_t)(b * 2 + half64) << 18);
                    const uint4 u0 = __ldg((const uint4*)(pl + (size_t)q.x * 64) + lane8);
                    const uint4 u1 = __ldg((const uint4*)(pl + (size_t)q.y * 64) + lane8);
                    const uint4 u2 = __ldg((const uint4*)(pl + (size_t)q.z * 64) + lane8);
                    const uint4 u3 = __ldg((const uint4*)(pl + (size_t)q.w * 64) + lane8);
                    const uint32_t* p0 = (const uint32_t*)&u0;
                    const uint32_t* p1 = (const uint32_t*)&u1;
                    const uint32_t* p2 = (const uint32_t*)&u2;
                    const uint32_t* p3 = (const uint32_t*)&u3;
                    uint4 st;
                    uint32_t* sv = (uint32_t*)&st;
                    #pragma unroll
                    for (int j = 0; j < 4; j++) {
                        __half2 r = __hmul2(w0, *(const __half2*)&p0[j]);
                        r = __hfma2(w1, *(const __half2*)&p1[j], r);
                        r = __hfma2(w2, *(const __half2*)&p2[j], r);
                        r = __hfma2(w3, *(const __half2*)&p3[j], r);
                        sv[j] = *(const uint32_t*)&r;
                    }
                    *(uint4*)(vb + pix * (KPADH * 2) + (half64 * 64 + lane8 * 8) * 2) = st;
                }
            }

            MEMBAR_CTA();           // drain STS before signaling full
            BAR_ARRIVE(1 + s);      // buffer s full
        }
    } else {
        // ================= CONSUMER: warps 0-3 (128 threads) =================
        const int m0  = wid << 5;     // warp cout base (32 wide)
        const int mb0 = wid << 1;     // warp m-block base (16-row blocks)
        const int grp = lane >> 2;
        const int t4  = lane & 3;
        const int lm_pix = (lane & 7) + ((lane >> 4) << 3);  // 0..15
        const int lm_k   = ((lane >> 3) & 1) * 8;            // 0 or 8

        float acc[2][8][4];
        #pragma unroll
        for (int mt = 0; mt < 2; mt++)
            #pragma unroll
            for (int nt = 0; nt < 8; nt++)
                #pragma unroll
                for (int q = 0; q < 4; q++) acc[mt][nt][q] = 0.0f;

        for (int c = 0; c < NPHASE; c++) {
            const int s = c % NSTAGE;
            BAR_SYNC(1 + s);        // wait buffer s full

            const uint32_t vb32 = sb + OFF_V0 + s * VTILE_BYTES;
            #pragma unroll
            for (int ks = 0; ks < 8; ks++) {
                const int g = c * 8 + ks;
                const uint4 A0 = __ldg(&g_wfh[(g * 8 + mb0    ) * 32 + lane]);
                const uint4 A1 = __ldg(&g_wfh[(g * 8 + mb0 + 1) * 32 + lane]);
                #pragma unroll
                for (int p = 0; p < 4; p++) {
                    const uint32_t addr = vb32
                        + (uint32_t)(p * 16 + lm_pix) * (KPADH * 2)
                        + (uint32_t)(ks * 16 + lm_k) * 2;
                    uint32_t r0, r1, r2, r3;
                    asm volatile(
                        "ldmatrix.sync.aligned.m8n8.x4.shared.b16 {%0,%1,%2,%3}, [%4];"
                        : "=r"(r0), "=r"(r1), "=r"(r2), "=r"(r3) : "r"(addr));
                    mma_f16(acc[0][p * 2],     A0, r0, r1);
                    mma_f16(acc[1][p * 2],     A1, r0, r1);
                    mma_f16(acc[0][p * 2 + 1], A0, r2, r3);
                    mma_f16(acc[1][p * 2 + 1], A1, r2, r3);
                }
            }
            // mma issue implies the LDSM reads of buffer s completed -> safe to recycle
            BAR_ARRIVE(4 + s);      // buffer s empty
        }

        // ---- epilogue: bias + store ----
        #pragma unroll
        for (int mt = 0; mt < 2; mt++) {
            const int r0 = m0 + mt * 16 + grp;
            const int r1 = r0 + 8;
            const float bv0 = bias[r0];
            const float bv1 = bias[r1];
            float* o0 = out + ((size_t)(b * COUT + r0)) * HW + ho * WW + 2 * t4;
            float* o1 = out + ((size_t)(b * COUT + r1)) * HW + ho * WW + 2 * t4;
            #pragma unroll
            for (int nt = 0; nt < 8; nt++) {
                *(float2*)(o0 + nt * 8) = make_float2(acc[mt][nt][0] + bv0, acc[mt][nt][1] + bv0);
                *(float2*)(o1 + nt * 8) = make_float2(acc[mt][nt][2] + bv1, acc[mt][nt][3] + bv1);
            }
        }
    }
}

// ---------------- launch ----------------
extern "C" void kernel_launch(void* const* d_in, const int* in_sizes, int n_in,
                              void* d_out, int out_size)
{
    const float* x      = (const float*)d_in[0];
    const float* offset = (const float*)d_in[1];
    const float* weight = (const float*)d_in[2];
    const float* bias   = (const float*)d_in[3];
    float* out = (float*)d_out;

    cudaFuncSetAttribute(deform_conv_mma_kernel,
                         cudaFuncAttributeMaxDynamicSharedMemorySize, SMEM_TOTAL);

    prep_all_kernel<<<2048 + 72, 256>>>(x, weight);
    deform_conv_mma_kernel<<<BB * 64, 256, SMEM_TOTAL>>>(offset, bias, out);
}